// round 1
// baseline (speedup 1.0000x reference)
#include <cuda_runtime.h>

#define NCOLS  8192
#define TARGET 7680
#define NWIN   513        // NCOLS - TARGET + 1
#define NT     512

__device__ __forceinline__ unsigned int f2key(float x) {
    unsigned int u = __float_as_uint(x);
    return (u & 0x80000000u) ? ~u : (u | 0x80000000u);
}
__device__ __forceinline__ float key2f(unsigned int k) {
    unsigned int u = (k & 0x80000000u) ? (k ^ 0x80000000u) : ~k;
    return __uint_as_float(u);
}

__device__ __forceinline__ void bitonic_sort_1024(unsigned int* sb, int tid) {
    for (unsigned int k = 2; k <= 1024; k <<= 1) {
        for (unsigned int j = k >> 1; j > 0; j >>= 1) {
            __syncthreads();
            #pragma unroll
            for (unsigned int i = tid; i < 1024; i += NT) {
                unsigned int l = i ^ j;
                if (l > i) {
                    unsigned int a = sb[i], b = sb[l];
                    bool up = ((i & k) == 0);
                    if ((a > b) == up) { sb[i] = b; sb[l] = a; }
                }
            }
        }
    }
    __syncthreads();
}

__global__ __launch_bounds__(NT)
void recall_window_kernel(const float* __restrict__ x,
                          float* __restrict__ out, int rows)
{
    __shared__ unsigned int skey[NCOLS];        // 32 KB: row as ordered keys
    __shared__ unsigned int hist[256];
    __shared__ unsigned int sbuf[1024];
    __shared__ float        bot[NWIN];
    __shared__ unsigned int s_sel[2];
    __shared__ unsigned int s_cnt;
    __shared__ unsigned long long s_best;

    const int tid  = threadIdx.x;
    const int lane = tid & 31;
    const int row  = blockIdx.x;

    // ---- load row, convert to order-preserving keys (vec4) ----
    const float4* x4 = reinterpret_cast<const float4*>(x + (size_t)row * NCOLS);
    uint4* k4 = reinterpret_cast<uint4*>(skey);
    for (int i = tid; i < NCOLS / 4; i += NT) {
        float4 v = x4[i];
        uint4 kk;
        kk.x = f2key(v.x); kk.y = f2key(v.y);
        kk.z = f2key(v.z); kk.w = f2key(v.w);
        k4[i] = kk;
    }
    if (tid == 0) s_best = ~0ull;
    __syncthreads();

    // ---- exact 4-level radix select: K_low = s[512], K_high = s[7679] ----
    unsigned int Ksel[2];
    const int kranks[2] = { NWIN - 1, TARGET - 1 };
    #pragma unroll
    for (int sel = 0; sel < 2; ++sel) {
        unsigned int prefix = 0u;
        int krem = kranks[sel];
        for (int level = 3; level >= 0; --level) {
            const int shift = level * 8;
            for (int i = tid; i < 256; i += NT) hist[i] = 0;
            __syncthreads();
            const unsigned int pmask =
                (level == 3) ? 0u : (0xFFFFFFFFu << (8 * (level + 1)));
            for (int i = tid; i < NCOLS; i += NT) {
                unsigned int ky  = skey[i];
                bool ok          = ((ky & pmask) == prefix);
                unsigned int bin = (ky >> shift) & 0xFFu;
                unsigned int pm  = __ballot_sync(0xffffffffu, ok);
                if (ok) {
                    // warp-aggregate same-bin atomics (heavy exponent clustering)
                    unsigned int peers = __match_any_sync(pm, bin);
                    if (lane == (__ffs(peers) - 1))
                        atomicAdd(&hist[bin], (unsigned int)__popc(peers));
                }
            }
            __syncthreads();
            if (tid == 0) {
                unsigned int cum = 0, b = 0;
                for (; b < 256u; ++b) {
                    unsigned int c = hist[b];
                    if (cum + c > (unsigned int)krem) break;
                    cum += c;
                }
                s_sel[0] = b;
                s_sel[1] = (unsigned int)krem - cum;
            }
            __syncthreads();
            prefix |= s_sel[0] << shift;
            krem    = (int)s_sel[1];
            __syncthreads();
        }
        Ksel[sel] = prefix;
    }
    const unsigned int Klow  = Ksel[0];
    const unsigned int Khigh = Ksel[1];

    // ---- gather bottom set: keys < Klow, fill to 513 with Klow, pad max ----
    if (tid == 0) s_cnt = 0;
    __syncthreads();
    for (int i = tid; i < NCOLS; i += NT) {
        unsigned int ky = skey[i];
        bool take = (ky < Klow);
        unsigned int m = __ballot_sync(0xffffffffu, take);
        unsigned int base = 0;
        if (lane == 0) base = atomicAdd(&s_cnt, (unsigned int)__popc(m));
        base = __shfl_sync(0xffffffffu, base, 0);
        if (take) sbuf[base + __popc(m & ((1u << lane) - 1u))] = ky;
    }
    __syncthreads();
    {
        int c = (int)s_cnt;   // <= 512
        for (int i = c + tid;    i < NWIN; i += NT) sbuf[i] = Klow;
        for (int i = NWIN + tid; i < 1024; i += NT) sbuf[i] = 0xFFFFFFFFu;
    }
    bitonic_sort_1024(sbuf, tid);
    for (int i = tid; i < NWIN; i += NT) bot[i] = key2f(sbuf[i]);
    __syncthreads();

    // ---- gather top set: keys > Khigh, fill to 513 with Khigh, pad min ----
    if (tid == 0) s_cnt = 0;
    __syncthreads();
    for (int i = tid; i < NCOLS; i += NT) {
        unsigned int ky = skey[i];
        bool take = (ky > Khigh);
        unsigned int m = __ballot_sync(0xffffffffu, take);
        unsigned int base = 0;
        if (lane == 0) base = atomicAdd(&s_cnt, (unsigned int)__popc(m));
        base = __shfl_sync(0xffffffffu, base, 0);
        if (take) sbuf[base + __popc(m & ((1u << lane) - 1u))] = ky;
    }
    __syncthreads();
    {
        int c = (int)s_cnt;   // <= 512
        for (int i = c + tid;    i < NWIN; i += NT) sbuf[i] = Khigh;
        for (int i = NWIN + tid; i < 1024; i += NT) sbuf[i] = 0u;
    }
    bitonic_sort_1024(sbuf, tid);
    // ascending: 511 sentinels first, then top set at sbuf[511 .. 1023]
    // top[j] == s[7679 + j] == key2f(sbuf[511 + j])

    // ---- lengths[i] = top[i] - bot[i]; first-index argmin via packed min ----
    unsigned long long best = ~0ull;
    for (int i = tid; i < NWIN; i += NT) {
        float len = key2f(sbuf[511 + i]) - bot[i];     // always >= 0
        unsigned long long p =
            ((unsigned long long)__float_as_uint(len) << 32) | (unsigned int)i;
        if (p < best) best = p;
    }
    #pragma unroll
    for (int off = 16; off; off >>= 1) {
        unsigned long long o = __shfl_down_sync(0xffffffffu, best, off);
        if (o < best) best = o;
    }
    if (lane == 0) atomicMin(&s_best, best);
    __syncthreads();

    if (tid == 0) {
        int idx = (int)(unsigned int)(s_best & 0xffffffffu);
        out[row]        = bot[idx];                    // left
        out[rows + row] = key2f(sbuf[511 + idx]);      // right
    }
}

extern "C" void kernel_launch(void* const* d_in, const int* in_sizes, int n_in,
                              void* d_out, int out_size) {
    const float* x = (const float*)d_in[0];
    float* out = (float*)d_out;
    int rows = in_sizes[0] / NCOLS;   // 4096
    recall_window_kernel<<<rows, NT>>>(x, out, rows);
}

// round 2
// speedup vs baseline: 2.0803x; 2.0803x over previous
#include <cuda_runtime.h>

#define NCOLS  8192
#define TARGET 7680
#define NWIN   513        // NCOLS - TARGET + 1
#define NT     256
#define NBINS  2048
#define BSHIFT 21         // top 11 bits of the order-preserving key

__device__ __forceinline__ unsigned int f2key(float x) {
    unsigned int u = __float_as_uint(x);
    return (u & 0x80000000u) ? ~u : (u | 0x80000000u);
}
__device__ __forceinline__ float key2f(unsigned int k) {
    unsigned int u = (k & 0x80000000u) ? (k ^ 0x80000000u) : ~k;
    return __uint_as_float(u);
}

__global__ __launch_bounds__(NT)
void recall_window_kernel(const float* __restrict__ x,
                          float* __restrict__ out, int rows)
{
    __shared__ unsigned int skey[NCOLS];      // 32 KB row keys
    __shared__ unsigned int scratch[2048];    // phase A: histogram; phase B: two 1024 sort buffers
    __shared__ unsigned int psum[NT];         // 8-bin group sums
    __shared__ unsigned int wbase[32];        // 64-bin superblock exclusive prefixes
    __shared__ unsigned int s_bin[2];         // B_low, B_high
    __shared__ unsigned int s_cnt[2];
    __shared__ unsigned long long s_best;

    const int tid  = threadIdx.x;
    const int lane = tid & 31;
    const int row  = blockIdx.x;

    // ---- phase 0: zero hist ----
    #pragma unroll
    for (int i = tid; i < NBINS; i += NT) scratch[i] = 0;
    if (tid == 0) s_best = ~0ull;
    __syncthreads();

    // ---- phase 1: load row, convert keys, histogram (single scan) ----
    const float4* x4 = reinterpret_cast<const float4*>(x + (size_t)row * NCOLS);
    uint4* k4 = reinterpret_cast<uint4*>(skey);
    #pragma unroll
    for (int i = tid; i < NCOLS / 4; i += NT) {       // 8 iters
        float4 v = x4[i];
        uint4 kk;
        kk.x = f2key(v.x); kk.y = f2key(v.y);
        kk.z = f2key(v.z); kk.w = f2key(v.w);
        k4[i] = kk;
        atomicAdd(&scratch[kk.x >> BSHIFT], 1u);
        atomicAdd(&scratch[kk.y >> BSHIFT], 1u);
        atomicAdd(&scratch[kk.z >> BSHIFT], 1u);
        atomicAdd(&scratch[kk.w >> BSHIFT], 1u);
    }
    __syncthreads();

    // ---- phase 2: parallel prefix + dual crossing search ----
    unsigned int h[8], gs = 0;
    #pragma unroll
    for (int j = 0; j < 8; ++j) { h[j] = scratch[8 * tid + j]; gs += h[j]; }
    psum[tid] = gs;
    __syncthreads();

    if (tid < 32) {
        unsigned int s8 = 0;
        #pragma unroll
        for (int j = 0; j < 8; ++j) s8 += psum[8 * tid + j];
        unsigned int inc = s8;
        #pragma unroll
        for (int off = 1; off < 32; off <<= 1) {
            unsigned int v = __shfl_up_sync(0xffffffffu, inc, off);
            if (lane >= off) inc += v;
        }
        wbase[tid] = inc - s8;          // exclusive superblock prefix
    }
    __syncthreads();

    {
        unsigned int base = wbase[tid >> 3];
        for (int j = (tid & ~7); j < tid; ++j) base += psum[j];
        #pragma unroll
        for (int sel = 0; sel < 2; ++sel) {
            const unsigned int tgt = sel ? (TARGET - 1) : (NWIN - 1);
            if (base <= tgt && tgt < base + gs) {
                unsigned int c = base;
                #pragma unroll
                for (int j = 0; j < 8; ++j) {
                    if (c + h[j] > tgt) { s_bin[sel] = 8 * tid + j; break; }
                    c += h[j];
                }
            }
        }
    }
    if (tid < 2) s_cnt[tid] = 0;
    __syncthreads();

    // ---- phase 3: single gather scan for both tails ----
    const unsigned int Blo = s_bin[0];
    const unsigned int Bhi = s_bin[1];
    for (int i = tid; i < NCOLS; i += NT) {           // 32 iters
        unsigned int ky = skey[i];
        unsigned int b  = ky >> BSHIFT;
        bool tl = (b <= Blo), th = (b >= Bhi);
        unsigned int ml = __ballot_sync(0xffffffffu, tl);
        unsigned int mh = __ballot_sync(0xffffffffu, th);
        unsigned int basel = 0, baseh = 0;
        if (lane == 0) {
            if (ml) basel = atomicAdd(&s_cnt[0], (unsigned int)__popc(ml));
            if (mh) baseh = atomicAdd(&s_cnt[1], (unsigned int)__popc(mh));
        }
        basel = __shfl_sync(0xffffffffu, basel, 0);
        baseh = __shfl_sync(0xffffffffu, baseh, 0);
        if (tl) {
            unsigned int p = basel + __popc(ml & ((1u << lane) - 1u));
            if (p < 1024) scratch[p] = ky;
        }
        if (th) {
            unsigned int p = baseh + __popc(mh & ((1u << lane) - 1u));
            if (p < 1024) scratch[1024 + p] = ky;
        }
    }
    __syncthreads();

    // ---- pad: lo with +inf-keys, hi with 0-keys ----
    {
        int cl = (int)min(s_cnt[0], 1024u);
        int ch = (int)min(s_cnt[1], 1024u);
        for (int i = cl + tid; i < 1024; i += NT) scratch[i]        = 0xFFFFFFFFu;
        for (int i = ch + tid; i < 1024; i += NT) scratch[1024 + i] = 0u;
    }

    // ---- phase 4: fused bitonic sort of both 1024 buffers (shared barriers) ----
    for (unsigned int k = 2; k <= 1024; k <<= 1) {
        for (unsigned int j = k >> 1; j > 0; j >>= 1) {
            __syncthreads();
            #pragma unroll
            for (unsigned int i = tid; i < 2048; i += NT) {
                unsigned int l = i ^ j;                 // stays within its 1024 segment
                if (l > i) {
                    unsigned int a = scratch[i], b = scratch[l];
                    bool up = (((i & 1023u) & k) == 0);
                    if ((a > b) == up) { scratch[i] = b; scratch[l] = a; }
                }
            }
        }
    }
    __syncthreads();
    // lo sorted: s[i] = scratch[i], i in [0,512]
    // hi sorted ascending with 0-pads first: s[7679+j] = scratch[1024 + 511 + j]

    // ---- phase 5: lengths + first-index argmin ----
    unsigned long long best = ~0ull;
    for (int i = tid; i < NWIN; i += NT) {
        float len = key2f(scratch[1024 + 511 + i]) - key2f(scratch[i]);
        unsigned long long p =
            ((unsigned long long)__float_as_uint(len) << 32) | (unsigned int)i;
        if (p < best) best = p;
    }
    #pragma unroll
    for (int off = 16; off; off >>= 1) {
        unsigned long long o = __shfl_down_sync(0xffffffffu, best, off);
        if (o < best) best = o;
    }
    if (lane == 0) atomicMin(&s_best, best);
    __syncthreads();

    if (tid == 0) {
        int idx = (int)(unsigned int)(s_best & 0xffffffffu);
        out[row]        = key2f(scratch[idx]);
        out[rows + row] = key2f(scratch[1024 + 511 + idx]);
    }
}

extern "C" void kernel_launch(void* const* d_in, const int* in_sizes, int n_in,
                              void* d_out, int out_size) {
    const float* x = (const float*)d_in[0];
    float* out = (float*)d_out;
    int rows = in_sizes[0] / NCOLS;   // 4096
    recall_window_kernel<<<rows, NT>>>(x, out, rows);
}

// round 3
// speedup vs baseline: 3.9379x; 1.8929x over previous
#include <cuda_runtime.h>

#define NCOLS  8192
#define TARGET 7680
#define NWIN   513
#define NT     256

__device__ __forceinline__ unsigned f2key(float x) {
    unsigned u = __float_as_uint(x);
    return (u & 0x80000000u) ? ~u : (u | 0x80000000u);
}
__device__ __forceinline__ float key2f(unsigned k) {
    unsigned u = (k & 0x80000000u) ? (k ^ 0x80000000u) : ~k;
    return __uint_as_float(u);
}

__device__ __forceinline__ void cas(unsigned& a, unsigned& b, bool up) {
    unsigned x = a, y = b;
    unsigned mn = min(x, y), mx = max(x, y);
    a = up ? mn : mx;
    b = up ? mx : mn;
}

__device__ __forceinline__ void sort8(unsigned v[8], bool up) {
    cas(v[0], v[4], up); cas(v[1], v[5], up); cas(v[2], v[6], up); cas(v[3], v[7], up);
    cas(v[0], v[2], up); cas(v[1], v[3], up); cas(v[4], v[6], up); cas(v[5], v[7], up);
    cas(v[0], v[1], up); cas(v[2], v[3], up); cas(v[4], v[5], up); cas(v[6], v[7], up);
}

__device__ __forceinline__ void shfl_pass(unsigned v[8], int delta, bool up, int ts) {
    bool keepmin = (up == ((ts & delta) == 0));
    #pragma unroll
    for (int e = 0; e < 8; ++e) {
        unsigned o = __shfl_xor_sync(0xffffffffu, v[e], delta);
        v[e] = keepmin ? min(v[e], o) : max(v[e], o);
    }
}

__device__ __forceinline__ void smem_pass(unsigned v[8], int delta, bool up,
                                          int t, int ts, unsigned* scratch) {
    __syncthreads();
    #pragma unroll
    for (int e = 0; e < 8; ++e) scratch[t * 8 + e] = v[e];
    __syncthreads();
    bool keepmin = (up == ((ts & delta) == 0));
    int pt = t ^ delta;
    #pragma unroll
    for (int e = 0; e < 8; ++e) {
        unsigned o = scratch[pt * 8 + e];
        v[e] = keepmin ? min(v[e], o) : max(v[e], o);
    }
}

// count of keys (<= K) if !ge, or (>= K) if ge, across the block
__device__ unsigned block_count(const float4* x4, unsigned K, bool ge,
                                unsigned* s_red, int tid) {
    if (tid == 0) *s_red = 0;
    __syncthreads();
    unsigned c = 0;
    for (int i = tid; i < NCOLS / 4; i += NT) {
        float4 w = x4[i];
        unsigned k0 = f2key(w.x), k1 = f2key(w.y), k2 = f2key(w.z), k3 = f2key(w.w);
        if (ge) c += (k0 >= K) + (k1 >= K) + (k2 >= K) + (k3 >= K);
        else    c += (k0 <= K) + (k1 <= K) + (k2 <= K) + (k3 <= K);
    }
    #pragma unroll
    for (int off = 16; off; off >>= 1) c += __shfl_down_sync(0xffffffffu, c, off);
    if ((tid & 31) == 0) atomicAdd(s_red, c);
    __syncthreads();
    unsigned r = *s_red;
    __syncthreads();
    return r;
}

// side 0: gather keys < T ; side 1: gather keys > T.  Returns raw count.
__device__ unsigned gather_side(const float4* x4, unsigned T, int side,
                                unsigned* seg, unsigned* s_c, int tid) {
    if (tid == 0) *s_c = 0;
    __syncthreads();
    const int lane = tid & 31;
    for (int i = tid; i < NCOLS / 4; i += NT) {
        float4 w = x4[i];
        unsigned kk[4] = { f2key(w.x), f2key(w.y), f2key(w.z), f2key(w.w) };
        #pragma unroll
        for (int q = 0; q < 4; ++q) {
            bool take = side ? (kk[q] > T) : (kk[q] < T);
            unsigned m = __ballot_sync(0xffffffffu, take);
            unsigned base = 0;
            if (lane == 0 && m) base = atomicAdd(s_c, (unsigned)__popc(m));
            base = __shfl_sync(0xffffffffu, base, 0);
            if (take) {
                unsigned p = base + __popc(m & ((1u << lane) - 1u));
                if (p < 1024) seg[p] = kk[q];
            }
        }
    }
    __syncthreads();
    unsigned r = *s_c;
    __syncthreads();
    return r;
}

__global__ __launch_bounds__(NT)
void recall_window_kernel(const float* __restrict__ x,
                          float* __restrict__ out, int rows)
{
    __shared__ unsigned scratch[2048];     // two 1024 sort segments
    __shared__ unsigned s_c;
    __shared__ unsigned long long s_best;

    const int t    = threadIdx.x;
    const int lane = t & 31;
    const int ts   = t & 127;              // thread index within 1024-segment
    const int row  = blockIdx.x;
    const float4* x4 = reinterpret_cast<const float4*>(x + (size_t)row * NCOLS);

    const unsigned kTlo = f2key(-1.31f);
    const unsigned kThi = f2key( 1.31f);

    // ---- low tail: keys < T_lo (expected ~778 for N(0,1); exact fallback otherwise) ----
    unsigned c0 = gather_side(x4, kTlo, 0, scratch, &s_c, t);
    if (c0 < 513u || c0 > 1024u) {
        unsigned Kcut;
        if (block_count(x4, 0u, false, &s_c, t) >= 513u) {
            Kcut = 0u;
        } else {
            unsigned X = 0;
            for (int b = 31; b >= 0; --b) {
                unsigned X2 = X | (1u << b);
                if (block_count(x4, X2, false, &s_c, t) < 513u) X = X2;
            }
            Kcut = X + 1u;             // exact rank-512 key
        }
        c0 = gather_side(x4, Kcut, 0, scratch, &s_c, t);
        for (int i = (int)c0 + t; i < 513; i += NT) scratch[i] = Kcut;
        c0 = 513u;
    }
    for (int i = (int)c0 + t; i < 1024; i += NT) scratch[i] = 0xFFFFFFFFu;

    // ---- high tail: keys > T_hi ----
    unsigned c1 = gather_side(x4, kThi, 1, scratch + 1024, &s_c, t);
    if (c1 < 513u || c1 > 1024u) {
        unsigned Y = 0;
        for (int b = 31; b >= 0; --b) {
            unsigned Y2 = Y | (1u << b);
            if (block_count(x4, Y2, true, &s_c, t) >= 513u) Y = Y2;
        }
        c1 = gather_side(x4, Y, 1, scratch + 1024, &s_c, t);
        for (int i = (int)c1 + t; i < 513; i += NT) scratch[1024 + i] = Y;
        c1 = 513u;
    }
    for (int i = (int)c1 + t; i < 1024; i += NT) scratch[1024 + i] = 0u;
    if (t == 0) s_best = ~0ull;
    __syncthreads();

    // ---- register-blocked bitonic: two independent 1024 sorts, 8 elems/thread ----
    unsigned v[8];
    #pragma unroll
    for (int e = 0; e < 8; ++e) v[e] = scratch[t * 8 + e];

    // k=2
    cas(v[0], v[1], true);  cas(v[2], v[3], false);
    cas(v[4], v[5], true);  cas(v[6], v[7], false);
    // k=4
    cas(v[0], v[2], true);  cas(v[1], v[3], true);
    cas(v[4], v[6], false); cas(v[5], v[7], false);
    cas(v[0], v[1], true);  cas(v[2], v[3], true);
    cas(v[4], v[5], false); cas(v[6], v[7], false);
    // k=8
    sort8(v, (ts & 1) == 0);

    #pragma unroll
    for (int kk = 16; kk <= 1024; kk <<= 1) {
        bool up = ((ts & (kk >> 3)) == 0);
        #pragma unroll
        for (int j = kk >> 1; j >= 8; j >>= 1) {
            int delta = j >> 3;
            if (delta >= 32) smem_pass(v, delta, up, t, ts, scratch);
            else             shfl_pass(v, delta, up, ts);
        }
        sort8(v, up);
    }

    __syncthreads();
    #pragma unroll
    for (int e = 0; e < 8; ++e) scratch[t * 8 + e] = v[e];
    __syncthreads();
    // seg0 sorted: s[i] = scratch[i], i in [0,512]
    // seg1 sorted asc (0-sentinels first): s[7679+j] = scratch[1024+511+j]

    // ---- lengths + first-index argmin ----
    unsigned long long best = ~0ull;
    for (int i = t; i < NWIN; i += NT) {
        float len = key2f(scratch[1024 + 511 + i]) - key2f(scratch[i]);
        unsigned long long p =
            ((unsigned long long)__float_as_uint(len) << 32) | (unsigned)i;
        if (p < best) best = p;
    }
    #pragma unroll
    for (int off = 16; off; off >>= 1) {
        unsigned long long o = __shfl_down_sync(0xffffffffu, best, off);
        if (o < best) best = o;
    }
    if (lane == 0) atomicMin(&s_best, best);
    __syncthreads();

    if (t == 0) {
        int idx = (int)(unsigned)(s_best & 0xffffffffu);
        out[row]        = key2f(scratch[idx]);
        out[rows + row] = key2f(scratch[1024 + 511 + idx]);
    }
}

extern "C" void kernel_launch(void* const* d_in, const int* in_sizes, int n_in,
                              void* d_out, int out_size) {
    const float* x = (const float*)d_in[0];
    float* out = (float*)d_out;
    int rows = in_sizes[0] / NCOLS;   // 4096
    recall_window_kernel<<<rows, NT>>>(x, out, rows);
}

// round 4
// speedup vs baseline: 6.6441x; 1.6872x over previous
#include <cuda_runtime.h>

#define NCOLS  8192
#define TARGET 7680
#define NWIN   513
#define NT     256
#define KPT    32          // keys per thread (NT*KPT == NCOLS)

__device__ __forceinline__ unsigned f2key(float x) {
    unsigned u = __float_as_uint(x);
    return (u & 0x80000000u) ? ~u : (u | 0x80000000u);
}
__device__ __forceinline__ float key2f(unsigned k) {
    unsigned u = (k & 0x80000000u) ? (k ^ 0x80000000u) : ~k;
    return __uint_as_float(u);
}

__device__ __forceinline__ void cas(unsigned& a, unsigned& b, bool up) {
    unsigned x = a, y = b;
    unsigned mn = min(x, y), mx = max(x, y);
    a = up ? mn : mx;
    b = up ? mx : mn;
}

__device__ __forceinline__ void sort8(unsigned v[8], bool up) {
    cas(v[0], v[4], up); cas(v[1], v[5], up); cas(v[2], v[6], up); cas(v[3], v[7], up);
    cas(v[0], v[2], up); cas(v[1], v[3], up); cas(v[4], v[6], up); cas(v[5], v[7], up);
    cas(v[0], v[1], up); cas(v[2], v[3], up); cas(v[4], v[5], up); cas(v[6], v[7], up);
}

__device__ __forceinline__ void shfl_pass(unsigned v[8], int delta, bool up, int ts) {
    bool keepmin = (up == ((ts & delta) == 0));
    #pragma unroll
    for (int e = 0; e < 8; ++e) {
        unsigned o = __shfl_xor_sync(0xffffffffu, v[e], delta);
        v[e] = keepmin ? min(v[e], o) : max(v[e], o);
    }
}

__device__ __forceinline__ void smem_pass(unsigned v[8], int delta, bool up,
                                          int t, int ts, unsigned* scratch) {
    __syncthreads();
    #pragma unroll
    for (int e = 0; e < 8; ++e) scratch[t * 8 + e] = v[e];
    __syncthreads();
    bool keepmin = (up == ((ts & delta) == 0));
    int pt = t ^ delta;
    #pragma unroll
    for (int e = 0; e < 8; ++e) {
        unsigned o = scratch[pt * 8 + e];
        v[e] = keepmin ? min(v[e], o) : max(v[e], o);
    }
}

// ---- exact fallback helpers (block-uniform, never taken for N(0,1) data) ----
__device__ unsigned block_count(const float4* x4, unsigned K, bool ge,
                                unsigned* s_red, int tid) {
    if (tid == 0) *s_red = 0;
    __syncthreads();
    unsigned c = 0;
    for (int i = tid; i < NCOLS / 4; i += NT) {
        float4 w = x4[i];
        unsigned k0 = f2key(w.x), k1 = f2key(w.y), k2 = f2key(w.z), k3 = f2key(w.w);
        if (ge) c += (k0 >= K) + (k1 >= K) + (k2 >= K) + (k3 >= K);
        else    c += (k0 <= K) + (k1 <= K) + (k2 <= K) + (k3 <= K);
    }
    #pragma unroll
    for (int off = 16; off; off >>= 1) c += __shfl_down_sync(0xffffffffu, c, off);
    if ((tid & 31) == 0) atomicAdd(s_red, c);
    __syncthreads();
    unsigned r = *s_red;
    __syncthreads();
    return r;
}

__device__ unsigned gather_side(const float4* x4, unsigned T, int side,
                                unsigned* seg, unsigned* s_c, int tid) {
    if (tid == 0) *s_c = 0;
    __syncthreads();
    const int lane = tid & 31;
    for (int i = tid; i < NCOLS / 4; i += NT) {
        float4 w = x4[i];
        unsigned kk[4] = { f2key(w.x), f2key(w.y), f2key(w.z), f2key(w.w) };
        #pragma unroll
        for (int q = 0; q < 4; ++q) {
            bool take = side ? (kk[q] > T) : (kk[q] < T);
            unsigned m = __ballot_sync(0xffffffffu, take);
            unsigned base = 0;
            if (lane == 0 && m) base = atomicAdd(s_c, (unsigned)__popc(m));
            base = __shfl_sync(0xffffffffu, base, 0);
            if (take) {
                unsigned p = base + __popc(m & ((1u << lane) - 1u));
                if (p < 1024) seg[p] = kk[q];
            }
        }
    }
    __syncthreads();
    unsigned r = *s_c;
    __syncthreads();
    return r;
}

__global__ __launch_bounds__(NT)
void recall_window_kernel(const float* __restrict__ x,
                          float* __restrict__ out, int rows)
{
    __shared__ unsigned scratch[2048];
    __shared__ unsigned wsum[8];
    __shared__ unsigned s_c;
    __shared__ unsigned long long s_best;

    const int t    = threadIdx.x;
    const int lane = t & 31;
    const int wid  = t >> 5;
    const int ts   = t & 127;
    const int row  = blockIdx.x;
    const float4* x4 = reinterpret_cast<const float4*>(x + (size_t)row * NCOLS);

    const unsigned kTlo = f2key(-1.31f);
    const unsigned kThi = f2key( 1.31f);

    // ---- phase 1: load 32 keys/thread into registers, count tail takes ----
    unsigned key[KPT];
    unsigned clo = 0, chi = 0;
    #pragma unroll
    for (int e4 = 0; e4 < KPT / 4; ++e4) {
        float4 w = x4[e4 * NT + t];
        key[e4 * 4 + 0] = f2key(w.x);
        key[e4 * 4 + 1] = f2key(w.y);
        key[e4 * 4 + 2] = f2key(w.z);
        key[e4 * 4 + 3] = f2key(w.w);
    }
    #pragma unroll
    for (int e = 0; e < KPT; ++e) {
        clo += (key[e] < kTlo);
        chi += (key[e] > kThi);
    }

    // ---- phase 2: block exclusive scan of packed (clo | chi<<16) ----
    unsigned packed = clo | (chi << 16);
    unsigned incl = packed;
    #pragma unroll
    for (int off = 1; off < 32; off <<= 1) {
        unsigned v = __shfl_up_sync(0xffffffffu, incl, off);
        if (lane >= off) incl += v;
    }
    if (lane == 31) wsum[wid] = incl;
    __syncthreads();
    unsigned wbase = 0, tot = 0;
    #pragma unroll
    for (int w = 0; w < 8; ++w) {
        unsigned s = wsum[w];
        if (w < wid) wbase += s;
        tot += s;
    }
    unsigned excl   = wbase + incl - packed;
    unsigned baselo = excl & 0xFFFFu, basehi = excl >> 16;
    unsigned totlo  = tot  & 0xFFFFu, tothi  = tot  >> 16;

    const bool ok_lo = (totlo >= 513u && totlo <= 1024u);
    const bool ok_hi = (tothi >= 513u && tothi <= 1024u);

    // ---- phase 3: direct register scatter (no ballots, no atomics) ----
    if (ok_lo && ok_hi) {
        unsigned plo = baselo, phi = basehi;
        #pragma unroll
        for (int e = 0; e < KPT; ++e) {
            unsigned k = key[e];
            if (k < kTlo)      scratch[plo++] = k;
            else if (k > kThi) scratch[1024 + phi++] = k;
        }
    }
    __syncthreads();

    unsigned c0 = totlo, c1 = tothi;
    if (!ok_lo) {                                   // exact fallback (cold)
        unsigned Kcut;
        if (block_count(x4, 0u, false, &s_c, t) >= 513u) {
            Kcut = 0u;
        } else {
            unsigned X = 0;
            for (int b = 31; b >= 0; --b) {
                unsigned X2 = X | (1u << b);
                if (block_count(x4, X2, false, &s_c, t) < 513u) X = X2;
            }
            Kcut = X + 1u;
        }
        c0 = gather_side(x4, Kcut, 0, scratch, &s_c, t);
        for (int i = (int)c0 + t; i < 513; i += NT) scratch[i] = Kcut;
        c0 = 513u;
    }
    if (!ok_hi) {
        unsigned Y = 0;
        for (int b = 31; b >= 0; --b) {
            unsigned Y2 = Y | (1u << b);
            if (block_count(x4, Y2, true, &s_c, t) >= 513u) Y = Y2;
        }
        c1 = gather_side(x4, Y, 1, scratch + 1024, &s_c, t);
        for (int i = (int)c1 + t; i < 513; i += NT) scratch[1024 + i] = Y;
        c1 = 513u;
    }
    // pad: lo with max-keys, hi with 0-keys
    for (int i = (int)c0 + t; i < 1024; i += NT) scratch[i]        = 0xFFFFFFFFu;
    for (int i = (int)c1 + t; i < 1024; i += NT) scratch[1024 + i] = 0u;
    if (t == 0) s_best = ~0ull;
    __syncthreads();

    // ---- phase 4: register-blocked bitonic, two independent 1024 sorts ----
    unsigned v[8];
    #pragma unroll
    for (int e = 0; e < 8; ++e) v[e] = scratch[t * 8 + e];

    cas(v[0], v[1], true);  cas(v[2], v[3], false);
    cas(v[4], v[5], true);  cas(v[6], v[7], false);
    cas(v[0], v[2], true);  cas(v[1], v[3], true);
    cas(v[4], v[6], false); cas(v[5], v[7], false);
    cas(v[0], v[1], true);  cas(v[2], v[3], true);
    cas(v[4], v[5], false); cas(v[6], v[7], false);
    sort8(v, (ts & 1) == 0);

    #pragma unroll
    for (int kk = 16; kk <= 1024; kk <<= 1) {
        bool up = ((ts & (kk >> 3)) == 0);
        #pragma unroll
        for (int j = kk >> 1; j >= 8; j >>= 1) {
            int delta = j >> 3;
            if (delta >= 32) smem_pass(v, delta, up, t, ts, scratch);
            else             shfl_pass(v, delta, up, ts);
        }
        sort8(v, up);
    }

    __syncthreads();
    #pragma unroll
    for (int e = 0; e < 8; ++e) scratch[t * 8 + e] = v[e];
    __syncthreads();

    // ---- phase 5: lengths + first-index argmin ----
    unsigned long long best = ~0ull;
    for (int i = t; i < NWIN; i += NT) {
        float len = key2f(scratch[1024 + 511 + i]) - key2f(scratch[i]);
        unsigned long long p =
            ((unsigned long long)__float_as_uint(len) << 32) | (unsigned)i;
        if (p < best) best = p;
    }
    #pragma unroll
    for (int off = 16; off; off >>= 1) {
        unsigned long long o = __shfl_down_sync(0xffffffffu, best, off);
        if (o < best) best = o;
    }
    if (lane == 0) atomicMin(&s_best, best);
    __syncthreads();

    if (t == 0) {
        int idx = (int)(unsigned)(s_best & 0xffffffffu);
        out[row]        = key2f(scratch[idx]);
        out[rows + row] = key2f(scratch[1024 + 511 + idx]);
    }
}

extern "C" void kernel_launch(void* const* d_in, const int* in_sizes, int n_in,
                              void* d_out, int out_size) {
    const float* x = (const float*)d_in[0];
    float* out = (float*)d_out;
    int rows = in_sizes[0] / NCOLS;   // 4096
    recall_window_kernel<<<rows, NT>>>(x, out, rows);
}